// round 15
// baseline (speedup 1.0000x reference)
#include <cuda_runtime.h>
#include <cuda_fp16.h>
#include <cstdint>

#define N_NODES  50000
#define N_EDGES  800000
#define N_GRAPHS 128
#define D        128
#define ELL_CAP  96

// ---------------- scratch (device globals; no allocation allowed) ----------
__device__ __half g_xb[N_NODES * D];   // x converted to fp16
__device__ __half g_hw[N_NODES * D];   // GEMM output (UNscaled h@W)
__device__ __half g_hb[N_NODES * D];   // activations
__device__ __half g_wt[3 * D * D];     // transposed weights [N][K] fp16
__device__ int    g_cnt[N_NODES];      // in-degree
__device__ float  g_dinv[N_NODES];
__device__ int    g_ell[N_NODES * ELL_CAP];  // padded neighbor lists
__device__ float  g_gs[N_GRAPHS * D];
__device__ float  g_gcnt[N_GRAPHS];

// ---------------- small helpers --------------------------------------------
__device__ __forceinline__ unsigned hpack(float lo, float hi) {
    unsigned r;
    asm("cvt.rn.f16x2.f32 %0, %1, %2;" : "=r"(r) : "f"(hi), "f"(lo));
    return r;
}
__device__ __forceinline__ float4 h2f4(uint2 p) {
    __half2 a = *reinterpret_cast<__half2*>(&p.x);
    __half2 b = *reinterpret_cast<__half2*>(&p.y);
    float2 fa = __half22float2(a);
    float2 fb = __half22float2(b);
    return make_float4(fa.x, fa.y, fb.x, fb.y);
}
// acc += s * val
__device__ __forceinline__ void fma4(float4& a, float s, float4 t) {
    a.x = fmaf(s, t.x, a.x); a.y = fmaf(s, t.y, a.y);
    a.z = fmaf(s, t.z, a.z); a.w = fmaf(s, t.w, a.w);
}
__device__ __forceinline__ uint32_t smem_u32(const void* p) {
    uint32_t a;
    asm("{ .reg .u64 t; cvta.to.shared.u64 t, %1; cvt.u32.u64 %0, t; }"
        : "=r"(a) : "l"(p));
    return a;
}

// ---------------- mma helpers ------------------------------------------------
__device__ __forceinline__ void ldsm_x4(uint32_t& r0, uint32_t& r1,
                                        uint32_t& r2, uint32_t& r3,
                                        uint32_t addr) {
    asm volatile("ldmatrix.sync.aligned.m8n8.x4.shared.b16 {%0,%1,%2,%3}, [%4];"
                 : "=r"(r0), "=r"(r1), "=r"(r2), "=r"(r3) : "r"(addr));
}
__device__ __forceinline__ void ldsm_x2(uint32_t& r0, uint32_t& r1,
                                        uint32_t addr) {
    asm volatile("ldmatrix.sync.aligned.m8n8.x2.shared.b16 {%0,%1}, [%2];"
                 : "=r"(r0), "=r"(r1) : "r"(addr));
}
__device__ __forceinline__ void mma16816(float& d0, float& d1, float& d2, float& d3,
                                         uint32_t a0, uint32_t a1, uint32_t a2,
                                         uint32_t a3, uint32_t b0, uint32_t b1) {
    asm volatile(
        "mma.sync.aligned.m16n8k16.row.col.f32.f16.f16.f32 "
        "{%0,%1,%2,%3}, {%4,%5,%6,%7}, {%8,%9}, {%0,%1,%2,%3};"
        : "+f"(d0), "+f"(d1), "+f"(d2), "+f"(d3)
        : "r"(a0), "r"(a1), "r"(a2), "r"(a3), "r"(b0), "r"(b1));
}

// ---------------- setup kernels --------------------------------------------
// ONE-pass graph build: ELL insert + per-graph node counts
__global__ void ell_build_kernel(const int* __restrict__ row,
                                 const int* __restrict__ col,
                                 const int* __restrict__ batch) {
    int i = blockIdx.x * blockDim.x + threadIdx.x;
    if (i < N_EDGES) {
        int c = col[i];
        int p = atomicAdd(&g_cnt[c], 1);
        if (p < ELL_CAP) g_ell[c * ELL_CAP + p] = row[i];
    }
    if (i < N_NODES) atomicAdd(&g_gcnt[batch[i]], 1.0f);
}

__global__ void dinv_kernel() {
    int i = blockIdx.x * blockDim.x + threadIdx.x;
    if (i < N_NODES) g_dinv[i] = rsqrtf((float)(g_cnt[i] + 1));
}

// convert x -> fp16 AND transpose+convert all 3 weight matrices (main stream)
__global__ void conv_kernel(const float* __restrict__ x,
                            const float* __restrict__ W1,
                            const float* __restrict__ W2,
                            const float* __restrict__ W3) {
    int i = blockIdx.x * blockDim.x + threadIdx.x;
    if (i < N_NODES * (D / 4)) {
        float4 v = ((const float4*)x)[i];
        uint2 o;
        o.x = hpack(v.x, v.y);
        o.y = hpack(v.z, v.w);
        ((uint2*)g_xb)[i] = o;
    }
    if (i < 3 * D * D) {
        int l = i >> 14;
        int r = i & (D * D - 1);
        int k = r >> 7, n = r & 127;
        const float* W = (l == 0) ? W1 : ((l == 1) ? W2 : W3);
        g_wt[l * D * D + n * D + k] = __float2half(W[k * D + n]);
    }
}

// ---------------- shared GEMM pieces ----------------------------------------
#define SM_STRIDE 136
#define SM_ROWB   (SM_STRIDE * 2)
#define SM_A_OFF  0
#define SM_B_OFF  (128 * SM_ROWB)
#define SM_TOT    (2 * 128 * SM_ROWB)

__device__ __forceinline__ void stage_B(char* smem, const __half* Wt, int tid) {
    const uint4* Bin = (const uint4*)Wt;
    #pragma unroll 4
    for (int i = tid; i < 2048; i += 256) {
        int r = i >> 4, g = i & 15;
        *(uint4*)(smem + SM_B_OFF + r * SM_ROWB + g * 16) = Bin[i];
    }
}

// MMA mainloop + epilogue (NO dinv scaling — raw h@W in fp16)
__device__ __forceinline__ void mma_body(char* smem, uint32_t sb,
                                         __half* __restrict__ out,
                                         int row0, int n, int wid, int lane) {
    int m_base = wid * 16;
    uint32_t a_addr = sb + SM_A_OFF
                    + (uint32_t)(m_base + (lane & 15)) * SM_ROWB
                    + (uint32_t)(lane >> 4) * 16;
    uint32_t b_addr = sb + SM_B_OFF
                    + (uint32_t)(lane & 7) * SM_ROWB
                    + (uint32_t)((lane >> 3) & 1) * 16;

    float acc[16][4];
    #pragma unroll
    for (int j = 0; j < 16; j++)
        #pragma unroll
        for (int q = 0; q < 4; q++) acc[j][q] = 0.f;

    #pragma unroll
    for (int kk = 0; kk < 8; kk++) {
        uint32_t a0, a1, a2, a3;
        ldsm_x4(a0, a1, a2, a3, a_addr + kk * 32);
        #pragma unroll
        for (int j = 0; j < 16; j++) {
            uint32_t b0, b1;
            ldsm_x2(b0, b1, b_addr + (uint32_t)j * 8 * SM_ROWB + kk * 32);
            mma16816(acc[j][0], acc[j][1], acc[j][2], acc[j][3],
                     a0, a1, a2, a3, b0, b1);
        }
    }

    int quad = lane >> 2;
    int tcol = (lane & 3) * 2;
    int r0 = row0 + m_base + quad;
    int r1 = r0 + 8;
    unsigned* o0 = (unsigned*)(out + (size_t)(r0 < n ? r0 : 0) * D);
    unsigned* o1 = (unsigned*)(out + (size_t)(r1 < n ? r1 : 0) * D);
    #pragma unroll
    for (int j = 0; j < 16; j++) {
        int nc = j * 8 + tcol;
        if (r0 < n) o0[nc >> 1] = hpack(acc[j][0], acc[j][1]);
        if (r1 < n) o1[nc >> 1] = hpack(acc[j][2], acc[j][3]);
    }
}

__global__ void __launch_bounds__(256, 2)
mma_gemm_kernel(const __half* __restrict__ in,
                const __half* __restrict__ Wt,
                __half* __restrict__ out, int n) {
    extern __shared__ char smem[];
    uint32_t sb = smem_u32(smem);
    int tid = threadIdx.x, wid = tid >> 5, lane = tid & 31;
    int row0 = blockIdx.x * 128;

    const uint4* Ain = (const uint4*)(in + (size_t)row0 * D);
    #pragma unroll 4
    for (int i = tid; i < 2048; i += 256) {
        int r = i >> 4, g = i & 15;
        uint4 va = make_uint4(0u, 0u, 0u, 0u);
        if (row0 + r < n) va = Ain[i];
        *(uint4*)(smem + SM_A_OFF + r * SM_ROWB + g * 16) = va;
    }
    stage_B(smem, Wt, tid);
    __syncthreads();
    mma_body(smem, sb, out, row0, n, wid, lane);
}

// ---------------- aggregation: warp/node, ELL gather with dinv[u] scaling ---
__global__ void agg_kernel(const uint2* __restrict__ hw,
                           const float* __restrict__ bias,
                           uint2* __restrict__ out, int relu) {
    int gt = blockIdx.x * blockDim.x + threadIdx.x;
    int v = gt >> 5;
    int lane = gt & 31;
    if (v >= N_NODES) return;

    float dv = g_dinv[v];
    float4 acc = make_float4(0.f, 0.f, 0.f, 0.f);
    fma4(acc, dv, h2f4(hw[v * 32 + lane]));    // self loop: dinv[v]*hw[v]
    const int* nb = g_ell + v * ELL_CAP;
    int e = g_cnt[v];
    int i = 0;
    for (; i + 8 <= e; i += 8) {
        int u0 = nb[i],     u1 = nb[i + 1];
        int u2 = nb[i + 2], u3 = nb[i + 3];
        int u4 = nb[i + 4], u5 = nb[i + 5];
        int u6 = nb[i + 6], u7 = nb[i + 7];
        uint2 p0 = hw[u0 * 32 + lane];
        uint2 p1 = hw[u1 * 32 + lane];
        uint2 p2 = hw[u2 * 32 + lane];
        uint2 p3 = hw[u3 * 32 + lane];
        uint2 p4 = hw[u4 * 32 + lane];
        uint2 p5 = hw[u5 * 32 + lane];
        uint2 p6 = hw[u6 * 32 + lane];
        uint2 p7 = hw[u7 * 32 + lane];
        fma4(acc, g_dinv[u0], h2f4(p0));
        fma4(acc, g_dinv[u1], h2f4(p1));
        fma4(acc, g_dinv[u2], h2f4(p2));
        fma4(acc, g_dinv[u3], h2f4(p3));
        fma4(acc, g_dinv[u4], h2f4(p4));
        fma4(acc, g_dinv[u5], h2f4(p5));
        fma4(acc, g_dinv[u6], h2f4(p6));
        fma4(acc, g_dinv[u7], h2f4(p7));
    }
    for (; i + 2 <= e; i += 2) {
        int u0 = nb[i], u1 = nb[i + 1];
        uint2 p0 = hw[u0 * 32 + lane];
        uint2 p1 = hw[u1 * 32 + lane];
        fma4(acc, g_dinv[u0], h2f4(p0));
        fma4(acc, g_dinv[u1], h2f4(p1));
    }
    if (i < e) {
        int u = nb[i];
        fma4(acc, g_dinv[u], h2f4(hw[u * 32 + lane]));
    }

    float4 b = ((const float4*)bias)[lane];
    float4 r;
    r.x = fmaf(dv, acc.x, b.x); r.y = fmaf(dv, acc.y, b.y);
    r.z = fmaf(dv, acc.z, b.z); r.w = fmaf(dv, acc.w, b.w);
    if (relu) {
        r.x = fmaxf(r.x, 0.f); r.y = fmaxf(r.y, 0.f);
        r.z = fmaxf(r.z, 0.f); r.w = fmaxf(r.w, 0.f);
    }
    out[v * 32 + lane] = make_uint2(hpack(r.x, r.y), hpack(r.z, r.w));
}

__global__ void agg_pool_kernel(const uint2* __restrict__ hw,
                                const float* __restrict__ bias,
                                const int* __restrict__ batch) {
    int gt = blockIdx.x * blockDim.x + threadIdx.x;
    int v = gt >> 5;
    int lane = gt & 31;
    if (v >= N_NODES) return;

    float dv = g_dinv[v];
    float4 acc = make_float4(0.f, 0.f, 0.f, 0.f);
    fma4(acc, dv, h2f4(hw[v * 32 + lane]));
    const int* nb = g_ell + v * ELL_CAP;
    int e = g_cnt[v];
    int i = 0;
    for (; i + 8 <= e; i += 8) {
        int u0 = nb[i],     u1 = nb[i + 1];
        int u2 = nb[i + 2], u3 = nb[i + 3];
        int u4 = nb[i + 4], u5 = nb[i + 5];
        int u6 = nb[i + 6], u7 = nb[i + 7];
        uint2 p0 = hw[u0 * 32 + lane];
        uint2 p1 = hw[u1 * 32 + lane];
        uint2 p2 = hw[u2 * 32 + lane];
        uint2 p3 = hw[u3 * 32 + lane];
        uint2 p4 = hw[u4 * 32 + lane];
        uint2 p5 = hw[u5 * 32 + lane];
        uint2 p6 = hw[u6 * 32 + lane];
        uint2 p7 = hw[u7 * 32 + lane];
        fma4(acc, g_dinv[u0], h2f4(p0));
        fma4(acc, g_dinv[u1], h2f4(p1));
        fma4(acc, g_dinv[u2], h2f4(p2));
        fma4(acc, g_dinv[u3], h2f4(p3));
        fma4(acc, g_dinv[u4], h2f4(p4));
        fma4(acc, g_dinv[u5], h2f4(p5));
        fma4(acc, g_dinv[u6], h2f4(p6));
        fma4(acc, g_dinv[u7], h2f4(p7));
    }
    for (; i + 2 <= e; i += 2) {
        int u0 = nb[i], u1 = nb[i + 1];
        uint2 p0 = hw[u0 * 32 + lane];
        uint2 p1 = hw[u1 * 32 + lane];
        fma4(acc, g_dinv[u0], h2f4(p0));
        fma4(acc, g_dinv[u1], h2f4(p1));
    }
    if (i < e) {
        int u = nb[i];
        fma4(acc, g_dinv[u], h2f4(hw[u * 32 + lane]));
    }

    float4 b = ((const float4*)bias)[lane];
    float4 r;
    r.x = fmaf(dv, acc.x, b.x); r.y = fmaf(dv, acc.y, b.y);
    r.z = fmaf(dv, acc.z, b.z); r.w = fmaf(dv, acc.w, b.w);

    int g = batch[v];
    float* base = &g_gs[g * D + lane * 4];
    atomicAdd(base + 0, r.x);
    atomicAdd(base + 1, r.y);
    atomicAdd(base + 2, r.z);
    atomicAdd(base + 3, r.w);
}

__global__ void final_kernel(const float* __restrict__ Wlin,
                             const float* __restrict__ blin,
                             float* __restrict__ out) {
    __shared__ float Ws[D * 3];
    int t = threadIdx.x;
    for (int i = t; i < D * 3; i += 128) Ws[i] = Wlin[i];
    __syncthreads();
    int g = t;
    float inv = 1.0f / fmaxf(g_gcnt[g], 1.0f);
    float o0 = blin[0], o1 = blin[1], o2 = blin[2];
    #pragma unroll 4
    for (int c = 0; c < D; ++c) {
        float p = g_gs[g * D + c] * inv;
        o0 = fmaf(p, Ws[c * 3 + 0], o0);
        o1 = fmaf(p, Ws[c * 3 + 1], o1);
        o2 = fmaf(p, Ws[c * 3 + 2], o2);
    }
    out[g * 3 + 0] = o0;
    out[g * 3 + 1] = o1;
    out[g * 3 + 2] = o2;
}

// ---------------- launch ----------------------------------------------------
extern "C" void kernel_launch(void* const* d_in, const int* in_sizes, int n_in,
                              void* d_out, int out_size) {
    const float* x     = (const float*)d_in[0];
    const int*   ei    = (const int*)d_in[1];
    const int*   batch = (const int*)d_in[2];
    const float* W1 = (const float*)d_in[3];
    const float* b1 = (const float*)d_in[4];
    const float* W2 = (const float*)d_in[5];
    const float* b2 = (const float*)d_in[6];
    const float* W3 = (const float*)d_in[7];
    const float* b3 = (const float*)d_in[8];
    const float* Wlin = (const float*)d_in[9];
    const float* blin = (const float*)d_in[10];
    float* out = (float*)d_out;

    const int* row = ei;
    const int* col = ei + N_EDGES;

    cudaFuncSetAttribute(mma_gemm_kernel,
                         cudaFuncAttributeMaxDynamicSharedMemorySize, SM_TOT);

    __half *xb_p = nullptr, *hw_p = nullptr, *hb_p = nullptr, *wt_p = nullptr;
    int *cnt_p = nullptr;
    float *gs_p = nullptr, *gcnt_p = nullptr;
    cudaGetSymbolAddress((void**)&xb_p, g_xb);
    cudaGetSymbolAddress((void**)&hw_p, g_hw);
    cudaGetSymbolAddress((void**)&hb_p, g_hb);
    cudaGetSymbolAddress((void**)&wt_p, g_wt);
    cudaGetSymbolAddress((void**)&cnt_p, g_cnt);
    cudaGetSymbolAddress((void**)&gs_p, g_gs);
    cudaGetSymbolAddress((void**)&gcnt_p, g_gcnt);

    static cudaStream_t s_side = nullptr;
    static cudaEvent_t  ev_fork = nullptr, ev_ready = nullptr;
    if (s_side == nullptr) {
        cudaStreamCreateWithFlags(&s_side, cudaStreamNonBlocking);
        cudaEventCreateWithFlags(&ev_fork,  cudaEventDisableTiming);
        cudaEventCreateWithFlags(&ev_ready, cudaEventDisableTiming);
    }

    const int edgeBlocks = (N_EDGES + 255) / 256;
    const int nodeBlocks = (N_NODES + 255) / 256;
    const int convBlocks = (N_NODES * 32 + 255) / 256;
    const int gemmGrid   = (N_NODES + 127) / 128;
    const int aggBlocks  = (N_NODES * 32 + 255) / 256;

    // fork side stream off the main (captured) stream
    cudaEventRecord(ev_fork, 0);
    cudaStreamWaitEvent(s_side, ev_fork, 0);

    // ---- side stream: one-pass ELL build ----
    cudaMemsetAsync(cnt_p,  0, N_NODES * sizeof(int), s_side);
    cudaMemsetAsync(gs_p,   0, N_GRAPHS * D * sizeof(float), s_side);
    cudaMemsetAsync(gcnt_p, 0, N_GRAPHS * sizeof(float), s_side);
    ell_build_kernel<<<edgeBlocks, 256, 0, s_side>>>(row, col, batch);
    dinv_kernel<<<nodeBlocks, 256, 0, s_side>>>();
    cudaEventRecord(ev_ready, s_side);   // ell + cnt + dinv + gcnt ready

    // ---- main stream ----
    conv_kernel<<<convBlocks, 256>>>(x, W1, W2, W3);
    // layer 1 GEMM no longer needs dinv — starts immediately after conv
    mma_gemm_kernel<<<gemmGrid, 256, SM_TOT>>>(xb_p, wt_p, hw_p, N_NODES);
    cudaStreamWaitEvent(0, ev_ready, 0);
    agg_kernel<<<aggBlocks, 256>>>((const uint2*)hw_p, b1, (uint2*)hb_p, 1);
    // layer 2
    mma_gemm_kernel<<<gemmGrid, 256, SM_TOT>>>(hb_p, wt_p + D * D, hw_p, N_NODES);
    agg_kernel<<<aggBlocks, 256>>>((const uint2*)hw_p, b2, (uint2*)hb_p, 1);
    // layer 3
    mma_gemm_kernel<<<gemmGrid, 256, SM_TOT>>>(hb_p, wt_p + 2 * D * D, hw_p, N_NODES);
    agg_pool_kernel<<<aggBlocks, 256>>>((const uint2*)hw_p, b3, batch);

    final_kernel<<<1, 128>>>(Wlin, blin, out);
}

// round 16
// speedup vs baseline: 1.2230x; 1.2230x over previous
#include <cuda_runtime.h>
#include <cuda_fp16.h>
#include <cstdint>

#define N_NODES  50000
#define N_EDGES  800000
#define N_GRAPHS 128
#define D        128
#define ELL_CAP  96

// ---------------- scratch (device globals; no allocation allowed) ----------
__device__ __half g_xb[N_NODES * D];   // x converted to fp16
__device__ __half g_hw[N_NODES * D];   // GEMM output (scaled by dinv)
__device__ __half g_hb[N_NODES * D];   // activations
__device__ __half g_wt[3 * D * D];     // transposed weights [N][K] fp16
__device__ int    g_cnt[N_NODES];      // in-degree
__device__ float  g_dinv[N_NODES];
__device__ int    g_ell[N_NODES * ELL_CAP];  // padded neighbor lists
__device__ float  g_gs[N_GRAPHS * D];
__device__ float  g_gcnt[N_GRAPHS];

// ---------------- small helpers --------------------------------------------
__device__ __forceinline__ unsigned hpack(float lo, float hi) {
    unsigned r;
    asm("cvt.rn.f16x2.f32 %0, %1, %2;" : "=r"(r) : "f"(hi), "f"(lo));
    return r;
}
__device__ __forceinline__ float4 h2f4(uint2 p) {
    __half2 a = *reinterpret_cast<__half2*>(&p.x);
    __half2 b = *reinterpret_cast<__half2*>(&p.y);
    float2 fa = __half22float2(a);
    float2 fb = __half22float2(b);
    return make_float4(fa.x, fa.y, fb.x, fb.y);
}
__device__ __forceinline__ void acc4(float4& a, float4 t) {
    a.x += t.x; a.y += t.y; a.z += t.z; a.w += t.w;
}
__device__ __forceinline__ uint32_t smem_u32(const void* p) {
    uint32_t a;
    asm("{ .reg .u64 t; cvta.to.shared.u64 t, %1; cvt.u32.u64 %0, t; }"
        : "=r"(a) : "l"(p));
    return a;
}

// ---------------- mma helpers ------------------------------------------------
__device__ __forceinline__ void ldsm_x4(uint32_t& r0, uint32_t& r1,
                                        uint32_t& r2, uint32_t& r3,
                                        uint32_t addr) {
    asm volatile("ldmatrix.sync.aligned.m8n8.x4.shared.b16 {%0,%1,%2,%3}, [%4];"
                 : "=r"(r0), "=r"(r1), "=r"(r2), "=r"(r3) : "r"(addr));
}
__device__ __forceinline__ void mma16816(float& d0, float& d1, float& d2, float& d3,
                                         uint32_t a0, uint32_t a1, uint32_t a2,
                                         uint32_t a3, uint32_t b0, uint32_t b1) {
    asm volatile(
        "mma.sync.aligned.m16n8k16.row.col.f32.f16.f16.f32 "
        "{%0,%1,%2,%3}, {%4,%5,%6,%7}, {%8,%9}, {%0,%1,%2,%3};"
        : "+f"(d0), "+f"(d1), "+f"(d2), "+f"(d3)
        : "r"(a0), "r"(a1), "r"(a2), "r"(a3), "r"(b0), "r"(b1));
}

// ---------------- setup kernels --------------------------------------------
// ONE-pass graph build: ELL insert + per-graph node counts
__global__ void ell_build_kernel(const int* __restrict__ row,
                                 const int* __restrict__ col,
                                 const int* __restrict__ batch) {
    int i = blockIdx.x * blockDim.x + threadIdx.x;
    if (i < N_EDGES) {
        int c = col[i];
        int p = atomicAdd(&g_cnt[c], 1);
        if (p < ELL_CAP) g_ell[c * ELL_CAP + p] = row[i];
    }
    if (i < N_NODES) atomicAdd(&g_gcnt[batch[i]], 1.0f);
}

__global__ void dinv_kernel() {
    int i = blockIdx.x * blockDim.x + threadIdx.x;
    if (i < N_NODES) g_dinv[i] = rsqrtf((float)(g_cnt[i] + 1));
}

// convert x -> fp16 AND transpose+convert all 3 weight matrices (main stream)
__global__ void conv_kernel(const float* __restrict__ x,
                            const float* __restrict__ W1,
                            const float* __restrict__ W2,
                            const float* __restrict__ W3) {
    int i = blockIdx.x * blockDim.x + threadIdx.x;
    if (i < N_NODES * (D / 4)) {
        float4 v = ((const float4*)x)[i];
        uint2 o;
        o.x = hpack(v.x, v.y);
        o.y = hpack(v.z, v.w);
        ((uint2*)g_xb)[i] = o;
    }
    if (i < 3 * D * D) {
        int l = i >> 14;
        int r = i & (D * D - 1);
        int k = r >> 7, n = r & 127;
        const float* W = (l == 0) ? W1 : ((l == 1) ? W2 : W3);
        g_wt[l * D * D + n * D + k] = __float2half(W[k * D + n]);
    }
}

// ---------------- shared GEMM pieces ----------------------------------------
#define SM_STRIDE 136
#define SM_ROWB   (SM_STRIDE * 2)
#define SM_A_OFF  0
#define SM_B_OFF  (128 * SM_ROWB)
#define SM_TOT    (2 * 128 * SM_ROWB)

__device__ __forceinline__ void stage_B(char* smem, const __half* Wt, int tid) {
    const uint4* Bin = (const uint4*)Wt;
    #pragma unroll 4
    for (int i = tid; i < 2048; i += 256) {
        int r = i >> 4, g = i & 15;
        *(uint4*)(smem + SM_B_OFF + r * SM_ROWB + g * 16) = Bin[i];
    }
}

// MMA mainloop + epilogue (dinv scaling in epilogue, R14 numerics).
// B fragments fetched two n-tiles per ldsm_x4 (lanes 16-31 -> second tile).
__device__ __forceinline__ void mma_body(char* smem, uint32_t sb,
                                         __half* __restrict__ out,
                                         int row0, int n, int wid, int lane) {
    int m_base = wid * 16;
    uint32_t a_addr = sb + SM_A_OFF
                    + (uint32_t)(m_base + (lane & 15)) * SM_ROWB
                    + (uint32_t)(lane >> 4) * 16;
    // x4 B mapping: row = (lane&7) + 8*(lane>>4), khalf = (lane>>3)&1
    uint32_t b_addr = sb + SM_B_OFF
                    + (uint32_t)((lane & 7) + ((lane >> 4) << 3)) * SM_ROWB
                    + (uint32_t)((lane >> 3) & 1) * 16;

    float acc[16][4];
    #pragma unroll
    for (int j = 0; j < 16; j++)
        #pragma unroll
        for (int q = 0; q < 4; q++) acc[j][q] = 0.f;

    #pragma unroll
    for (int kk = 0; kk < 8; kk++) {
        uint32_t a0, a1, a2, a3;
        ldsm_x4(a0, a1, a2, a3, a_addr + kk * 32);
        #pragma unroll
        for (int jp = 0; jp < 8; jp++) {
            uint32_t b0, b1, b2, b3;
            ldsm_x4(b0, b1, b2, b3,
                    b_addr + (uint32_t)jp * 16 * SM_ROWB + kk * 32);
            int j0 = jp * 2;
            mma16816(acc[j0][0], acc[j0][1], acc[j0][2], acc[j0][3],
                     a0, a1, a2, a3, b0, b1);
            mma16816(acc[j0 + 1][0], acc[j0 + 1][1],
                     acc[j0 + 1][2], acc[j0 + 1][3],
                     a0, a1, a2, a3, b2, b3);
        }
    }

    int quad = lane >> 2;
    int tcol = (lane & 3) * 2;
    int r0 = row0 + m_base + quad;
    int r1 = r0 + 8;
    float dv0 = (r0 < n) ? g_dinv[r0] : 0.f;
    float dv1 = (r1 < n) ? g_dinv[r1] : 0.f;
    unsigned* o0 = (unsigned*)(out + (size_t)(r0 < n ? r0 : 0) * D);
    unsigned* o1 = (unsigned*)(out + (size_t)(r1 < n ? r1 : 0) * D);
    #pragma unroll
    for (int j = 0; j < 16; j++) {
        int nc = j * 8 + tcol;
        if (r0 < n) o0[nc >> 1] = hpack(acc[j][0] * dv0, acc[j][1] * dv0);
        if (r1 < n) o1[nc >> 1] = hpack(acc[j][2] * dv1, acc[j][3] * dv1);
    }
}

__global__ void __launch_bounds__(256, 2)
mma_gemm_kernel(const __half* __restrict__ in,
                const __half* __restrict__ Wt,
                __half* __restrict__ out, int n) {
    extern __shared__ char smem[];
    uint32_t sb = smem_u32(smem);
    int tid = threadIdx.x, wid = tid >> 5, lane = tid & 31;
    int row0 = blockIdx.x * 128;

    const uint4* Ain = (const uint4*)(in + (size_t)row0 * D);
    #pragma unroll 4
    for (int i = tid; i < 2048; i += 256) {
        int r = i >> 4, g = i & 15;
        uint4 va = make_uint4(0u, 0u, 0u, 0u);
        if (row0 + r < n) va = Ain[i];
        *(uint4*)(smem + SM_A_OFF + r * SM_ROWB + g * 16) = va;
    }
    stage_B(smem, Wt, tid);
    __syncthreads();
    mma_body(smem, sb, out, row0, n, wid, lane);
}

// ---------------- aggregation: warp per node, ELL gather, fp32 acc ---------
// (R14-exact: hw rows are pre-scaled by dinv in the GEMM epilogue)
__global__ void agg_kernel(const uint2* __restrict__ hw,
                           const float* __restrict__ bias,
                           uint2* __restrict__ out, int relu) {
    int gt = blockIdx.x * blockDim.x + threadIdx.x;
    int v = gt >> 5;
    int lane = gt & 31;
    if (v >= N_NODES) return;

    float4 acc = h2f4(hw[v * 32 + lane]);      // self loop
    const int* nb = g_ell + v * ELL_CAP;
    int e = g_cnt[v];
    int i = 0;
    for (; i + 8 <= e; i += 8) {
        int u0 = nb[i],     u1 = nb[i + 1];
        int u2 = nb[i + 2], u3 = nb[i + 3];
        int u4 = nb[i + 4], u5 = nb[i + 5];
        int u6 = nb[i + 6], u7 = nb[i + 7];
        uint2 p0 = hw[u0 * 32 + lane];
        uint2 p1 = hw[u1 * 32 + lane];
        uint2 p2 = hw[u2 * 32 + lane];
        uint2 p3 = hw[u3 * 32 + lane];
        uint2 p4 = hw[u4 * 32 + lane];
        uint2 p5 = hw[u5 * 32 + lane];
        uint2 p6 = hw[u6 * 32 + lane];
        uint2 p7 = hw[u7 * 32 + lane];
        acc4(acc, h2f4(p0)); acc4(acc, h2f4(p1));
        acc4(acc, h2f4(p2)); acc4(acc, h2f4(p3));
        acc4(acc, h2f4(p4)); acc4(acc, h2f4(p5));
        acc4(acc, h2f4(p6)); acc4(acc, h2f4(p7));
    }
    for (; i + 2 <= e; i += 2) {
        int u0 = nb[i], u1 = nb[i + 1];
        uint2 p0 = hw[u0 * 32 + lane];
        uint2 p1 = hw[u1 * 32 + lane];
        acc4(acc, h2f4(p0)); acc4(acc, h2f4(p1));
    }
    if (i < e) acc4(acc, h2f4(hw[nb[i] * 32 + lane]));

    float dv = g_dinv[v];
    float4 b = ((const float4*)bias)[lane];
    float4 r;
    r.x = fmaf(dv, acc.x, b.x); r.y = fmaf(dv, acc.y, b.y);
    r.z = fmaf(dv, acc.z, b.z); r.w = fmaf(dv, acc.w, b.w);
    if (relu) {
        r.x = fmaxf(r.x, 0.f); r.y = fmaxf(r.y, 0.f);
        r.z = fmaxf(r.z, 0.f); r.w = fmaxf(r.w, 0.f);
    }
    out[v * 32 + lane] = make_uint2(hpack(r.x, r.y), hpack(r.z, r.w));
}

__global__ void agg_pool_kernel(const uint2* __restrict__ hw,
                                const float* __restrict__ bias,
                                const int* __restrict__ batch) {
    int gt = blockIdx.x * blockDim.x + threadIdx.x;
    int v = gt >> 5;
    int lane = gt & 31;
    if (v >= N_NODES) return;

    float4 acc = h2f4(hw[v * 32 + lane]);
    const int* nb = g_ell + v * ELL_CAP;
    int e = g_cnt[v];
    int i = 0;
    for (; i + 8 <= e; i += 8) {
        int u0 = nb[i],     u1 = nb[i + 1];
        int u2 = nb[i + 2], u3 = nb[i + 3];
        int u4 = nb[i + 4], u5 = nb[i + 5];
        int u6 = nb[i + 6], u7 = nb[i + 7];
        uint2 p0 = hw[u0 * 32 + lane];
        uint2 p1 = hw[u1 * 32 + lane];
        uint2 p2 = hw[u2 * 32 + lane];
        uint2 p3 = hw[u3 * 32 + lane];
        uint2 p4 = hw[u4 * 32 + lane];
        uint2 p5 = hw[u5 * 32 + lane];
        uint2 p6 = hw[u6 * 32 + lane];
        uint2 p7 = hw[u7 * 32 + lane];
        acc4(acc, h2f4(p0)); acc4(acc, h2f4(p1));
        acc4(acc, h2f4(p2)); acc4(acc, h2f4(p3));
        acc4(acc, h2f4(p4)); acc4(acc, h2f4(p5));
        acc4(acc, h2f4(p6)); acc4(acc, h2f4(p7));
    }
    for (; i + 2 <= e; i += 2) {
        int u0 = nb[i], u1 = nb[i + 1];
        uint2 p0 = hw[u0 * 32 + lane];
        uint2 p1 = hw[u1 * 32 + lane];
        acc4(acc, h2f4(p0)); acc4(acc, h2f4(p1));
    }
    if (i < e) acc4(acc, h2f4(hw[nb[i] * 32 + lane]));

    float dv = g_dinv[v];
    float4 b = ((const float4*)bias)[lane];
    float4 r;
    r.x = fmaf(dv, acc.x, b.x); r.y = fmaf(dv, acc.y, b.y);
    r.z = fmaf(dv, acc.z, b.z); r.w = fmaf(dv, acc.w, b.w);

    int g = batch[v];
    float* base = &g_gs[g * D + lane * 4];
    atomicAdd(base + 0, r.x);
    atomicAdd(base + 1, r.y);
    atomicAdd(base + 2, r.z);
    atomicAdd(base + 3, r.w);
}

__global__ void final_kernel(const float* __restrict__ Wlin,
                             const float* __restrict__ blin,
                             float* __restrict__ out) {
    __shared__ float Ws[D * 3];
    int t = threadIdx.x;
    for (int i = t; i < D * 3; i += 128) Ws[i] = Wlin[i];
    __syncthreads();
    int g = t;
    float inv = 1.0f / fmaxf(g_gcnt[g], 1.0f);
    float o0 = blin[0], o1 = blin[1], o2 = blin[2];
    #pragma unroll 4
    for (int c = 0; c < D; ++c) {
        float p = g_gs[g * D + c] * inv;
        o0 = fmaf(p, Ws[c * 3 + 0], o0);
        o1 = fmaf(p, Ws[c * 3 + 1], o1);
        o2 = fmaf(p, Ws[c * 3 + 2], o2);
    }
    out[g * 3 + 0] = o0;
    out[g * 3 + 1] = o1;
    out[g * 3 + 2] = o2;
}

// ---------------- launch ----------------------------------------------------
extern "C" void kernel_launch(void* const* d_in, const int* in_sizes, int n_in,
                              void* d_out, int out_size) {
    const float* x     = (const float*)d_in[0];
    const int*   ei    = (const int*)d_in[1];
    const int*   batch = (const int*)d_in[2];
    const float* W1 = (const float*)d_in[3];
    const float* b1 = (const float*)d_in[4];
    const float* W2 = (const float*)d_in[5];
    const float* b2 = (const float*)d_in[6];
    const float* W3 = (const float*)d_in[7];
    const float* b3 = (const float*)d_in[8];
    const float* Wlin = (const float*)d_in[9];
    const float* blin = (const float*)d_in[10];
    float* out = (float*)d_out;

    const int* row = ei;
    const int* col = ei + N_EDGES;

    cudaFuncSetAttribute(mma_gemm_kernel,
                         cudaFuncAttributeMaxDynamicSharedMemorySize, SM_TOT);

    __half *xb_p = nullptr, *hw_p = nullptr, *hb_p = nullptr, *wt_p = nullptr;
    int *cnt_p = nullptr;
    float *gs_p = nullptr, *gcnt_p = nullptr;
    cudaGetSymbolAddress((void**)&xb_p, g_xb);
    cudaGetSymbolAddress((void**)&hw_p, g_hw);
    cudaGetSymbolAddress((void**)&hb_p, g_hb);
    cudaGetSymbolAddress((void**)&wt_p, g_wt);
    cudaGetSymbolAddress((void**)&cnt_p, g_cnt);
    cudaGetSymbolAddress((void**)&gs_p, g_gs);
    cudaGetSymbolAddress((void**)&gcnt_p, g_gcnt);

    static cudaStream_t s_side = nullptr;
    static cudaEvent_t  ev_fork = nullptr, ev_ready = nullptr;
    if (s_side == nullptr) {
        cudaStreamCreateWithFlags(&s_side, cudaStreamNonBlocking);
        cudaEventCreateWithFlags(&ev_fork,  cudaEventDisableTiming);
        cudaEventCreateWithFlags(&ev_ready, cudaEventDisableTiming);
    }

    const int edgeBlocks = (N_EDGES + 255) / 256;
    const int nodeBlocks = (N_NODES + 255) / 256;
    const int convBlocks = (N_NODES * 32 + 255) / 256;
    const int gemmGrid   = (N_NODES + 127) / 128;
    const int aggBlocks  = (N_NODES * 32 + 255) / 256;

    // fork side stream off the main (captured) stream
    cudaEventRecord(ev_fork, 0);
    cudaStreamWaitEvent(s_side, ev_fork, 0);

    // ---- side stream: one-pass ELL build ----
    cudaMemsetAsync(cnt_p,  0, N_NODES * sizeof(int), s_side);
    cudaMemsetAsync(gs_p,   0, N_GRAPHS * D * sizeof(float), s_side);
    cudaMemsetAsync(gcnt_p, 0, N_GRAPHS * sizeof(float), s_side);
    ell_build_kernel<<<edgeBlocks, 256, 0, s_side>>>(row, col, batch);
    dinv_kernel<<<nodeBlocks, 256, 0, s_side>>>();
    cudaEventRecord(ev_ready, s_side);   // ell + cnt + dinv + gcnt ready

    // ---- main stream ----
    conv_kernel<<<convBlocks, 256>>>(x, W1, W2, W3);
    cudaStreamWaitEvent(0, ev_ready, 0);
    // layer 1
    mma_gemm_kernel<<<gemmGrid, 256, SM_TOT>>>(xb_p, wt_p, hw_p, N_NODES);
    agg_kernel<<<aggBlocks, 256>>>((const uint2*)hw_p, b1, (uint2*)hb_p, 1);
    // layer 2
    mma_gemm_kernel<<<gemmGrid, 256, SM_TOT>>>(hb_p, wt_p + D * D, hw_p, N_NODES);
    agg_kernel<<<aggBlocks, 256>>>((const uint2*)hw_p, b2, (uint2*)hb_p, 1);
    // layer 3
    mma_gemm_kernel<<<gemmGrid, 256, SM_TOT>>>(hb_p, wt_p + 2 * D * D, hw_p, N_NODES);
    agg_pool_kernel<<<aggBlocks, 256>>>((const uint2*)hw_p, b3, batch);

    final_kernel<<<1, 128>>>(Wlin, blin, out);
}